// round 3
// baseline (speedup 1.0000x reference)
#include <cuda_runtime.h>

#define FULL 0xffffffffu

__device__ __forceinline__ float wsum(float v){
  #pragma unroll
  for (int o = 16; o; o >>= 1) v += __shfl_xor_sync(FULL, v, o);
  return v;
}
__device__ __forceinline__ float wmax(float v){
  #pragma unroll
  for (int o = 16; o; o >>= 1) v = fmaxf(v, __shfl_xor_sync(FULL, v, o));
  return v;
}

// ---- shared memory layout (floats) ----
#define S_WH    0                    // 128x64 : Wh1, later Wh2
#define S_H1    (S_WH  + 128*64)     // 128x64 : h1 (post-LN)
#define S_W2    (S_H1  + 128*64)     // 64x64
#define S_Q     (S_W2  + 64*64)      // 8 warps x 4 rows x 128
#define S_C     (S_Q   + 8*4*128)    // 128
#define S_S     (S_C   + 128)        // 128
#define S_T     (S_S   + 128)        // 128
#define S_W1    (S_T   + 128)        // 9x64 = 576
#define S_EMB   (S_W1  + 576)        // 128x8 = 1024
#define S_XM    (S_EMB + 1024)       // 64
#define S_G1    (S_XM  + 64)         // 64
#define S_Y     (S_G1  + 64)         // 64
#define S_ACC   (S_Y   + 64)         // 1 (+pad)
#define SMEM_FLOATS (S_ACC + 8)

__global__ void __launch_bounds__(256, 2)
graphmixer_kernel(const float* __restrict__ gC,   const float* __restrict__ gAdj,
                  const float* __restrict__ gEmb, const float* __restrict__ gW1,
                  const float* __restrict__ gA1,  const float* __restrict__ gW2,
                  const float* __restrict__ gA2,  const float* __restrict__ gLn1g,
                  const float* __restrict__ gLn1b,const float* __restrict__ gLn2g,
                  const float* __restrict__ gLn2b,const float* __restrict__ gHgw,
                  const float* __restrict__ gHgb, const float* __restrict__ gM1w,
                  const float* __restrict__ gM1b, const float* __restrict__ gM2w,
                  const float* __restrict__ gM2b, const float* __restrict__ gHmw,
                  const float* __restrict__ gHmb, const float* __restrict__ gG1w,
                  const float* __restrict__ gG1b, const float* __restrict__ gG2w,
                  const float* __restrict__ gG2b, float* __restrict__ gOut)
{
  extern __shared__ float sm[];
  const int tid  = threadIdx.x;
  const int w    = tid >> 5;
  const int lane = tid & 31;
  const int b    = blockIdx.x;

  // ---------------- stage 0: stage constants into SMEM ----------------
  if (tid < 128) sm[S_C + tid] = gC[b*128 + tid];
  for (int i = tid; i < 576;  i += 256) sm[S_W1  + i] = gW1[i];
  for (int i = tid; i < 1024; i += 256) sm[S_EMB + i] = gEmb[i];
  for (int i = tid; i < 4096; i += 256) sm[S_W2  + i] = gW2[i];
  if (tid == 0) sm[S_ACC] = 0.f;
  __syncthreads();

  // ---------------- stage 1: Wh1 = [c | emb] @ W1  (128x9 @ 9x64) -----
  for (int idx = tid; idx < 8192; idx += 256) {
    int n = idx >> 6, h = idx & 63;
    float v = sm[S_C + n] * sm[S_W1 + h];
    #pragma unroll
    for (int d = 0; d < 8; d++)
      v += sm[S_EMB + n*8 + d] * sm[S_W1 + (d+1)*64 + h];
    sm[S_WH + idx] = v;
  }
  // MLP / gate hidden layers (only depend on sC)
  if (tid < 64) {
    float acc = gM1b[tid];
    #pragma unroll 4
    for (int n = 0; n < 128; n++) acc += sm[S_C + n] * __ldg(&gM1w[n*64 + tid]);
    sm[S_XM + tid] = fmaxf(acc, 0.f);
  } else if (tid < 128) {
    int h = tid - 64;
    float acc = gG1b[h];
    #pragma unroll 4
    for (int n = 0; n < 128; n++) acc += sm[S_C + n] * __ldg(&gG1w[n*64 + h]);
    sm[S_G1 + h] = fmaxf(acc, 0.f);
  }
  __syncthreads();

  // ---------------- stage 2: s1/t1 = Wh1 @ a_i, Wh1 @ a_j -------------
  {
    float aI0 = gA1[lane],      aI1 = gA1[32 + lane];
    float aJ0 = gA1[64 + lane], aJ1 = gA1[96 + lane];
    for (int r = 0; r < 16; r++) {
      int i = w*16 + r;
      float x0 = sm[S_WH + i*64 + lane], x1 = sm[S_WH + i*64 + 32 + lane];
      float sp = wsum(x0*aI0 + x1*aI1);
      float tp = wsum(x0*aJ0 + x1*aJ1);
      if (lane == 0) { sm[S_S + i] = sp; sm[S_T + i] = tp; }
    }
  }
  // MLP second layer
  if (tid < 64) {
    float acc = gM2b[tid];
    #pragma unroll 8
    for (int k = 0; k < 64; k++) acc += sm[S_XM + k] * __ldg(&gM2w[k*64 + tid]);
    sm[S_Y + tid] = fmaxf(acc, 0.f);
  }
  __syncthreads();

  // ---------------- stage 3: GAT layer 1 (attn + agg + elu + LN) ------
  for (int g = 0; g < 4; g++) {
    const int base = g*32 + w*4;            // 4 rows per warp per pass
    float scale[4];
    #pragma unroll
    for (int r = 0; r < 4; r++) {
      const int i = base + r;
      const float si = sm[S_S + i];
      float e[4], av[4];
      float m = -1e30f;
      #pragma unroll
      for (int jj = 0; jj < 4; jj++) {
        int j = jj*32 + lane;
        float ee = si + sm[S_T + j];
        ee = fmaxf(ee, 0.2f*ee);            // leaky_relu(x, 0.2)
        float a = __ldg(&gAdj[i*128 + j]);
        e[jj] = ee; av[jj] = a;
        m = fmaxf(m, a > 0.f ? ee : -1e30f);
      }
      m = wmax(m);
      float Sl = 0.f, Tl = 0.f;
      #pragma unroll
      for (int jj = 0; jj < 4; jj++) {
        float p = av[jj] > 0.f ? __expf(e[jj] - m) : 0.f;
        float q = av[jj] * p;
        Sl += p; Tl += q;
        sm[S_Q + (w*4 + r)*128 + jj*32 + lane] = q;
      }
      Sl = wsum(Sl); Tl = wsum(Tl);
      // softmax -> *adj -> renorm folded: h' = (sum q_j Wh_j) / (T + 1e-8*S)
      scale[r] = 1.f / (Tl + 1e-8f * Sl);
    }
    __syncwarp();
    float ax[4] = {0,0,0,0}, ay[4] = {0,0,0,0};
    const float* qbase = &sm[S_Q + w*4*128];
    for (int j4 = 0; j4 < 128; j4 += 4) {
      float4 q0 = *(const float4*)(qbase + 0*128 + j4);
      float4 q1 = *(const float4*)(qbase + 1*128 + j4);
      float4 q2 = *(const float4*)(qbase + 2*128 + j4);
      float4 q3 = *(const float4*)(qbase + 3*128 + j4);
      #pragma unroll
      for (int u = 0; u < 4; u++) {
        float2 whv = *(const float2*)&sm[S_WH + (j4+u)*64 + 2*lane];
        float f0 = (&q0.x)[u], f1 = (&q1.x)[u], f2 = (&q2.x)[u], f3 = (&q3.x)[u];
        ax[0] += f0*whv.x; ay[0] += f0*whv.y;
        ax[1] += f1*whv.x; ay[1] += f1*whv.y;
        ax[2] += f2*whv.x; ay[2] += f2*whv.y;
        ax[3] += f3*whv.x; ay[3] += f3*whv.y;
      }
    }
    #pragma unroll
    for (int r = 0; r < 4; r++) {
      const int i = base + r;
      float v0 = ax[r]*scale[r], v1 = ay[r]*scale[r];
      v0 = v0 > 0.f ? v0 : expm1f(v0);       // elu
      v1 = v1 > 0.f ? v1 : expm1f(v1);
      float mu  = wsum(v0 + v1) * (1.f/64.f);
      float d0 = v0 - mu, d1 = v1 - mu;
      float var = wsum(d0*d0 + d1*d1) * (1.f/64.f);
      float inv = rsqrtf(var + 1e-5f);
      float y0 = d0*inv*__ldg(&gLn1g[2*lane])   + __ldg(&gLn1b[2*lane]);
      float y1 = d1*inv*__ldg(&gLn1g[2*lane+1]) + __ldg(&gLn1b[2*lane+1]);
      *(float2*)&sm[S_H1 + i*64 + 2*lane] = make_float2(y0, y1);
    }
    __syncwarp();
  }
  __syncthreads();

  // ---------------- stage 4: Wh2 = h1 @ W2 (128x64 @ 64x64) -----------
  for (int g = 0; g < 4; g++) {
    const int base = g*32 + w*4;
    float ax[4] = {0,0,0,0}, ay[4] = {0,0,0,0};
    for (int k4 = 0; k4 < 64; k4 += 4) {
      float4 h0 = *(const float4*)&sm[S_H1 + (base+0)*64 + k4];
      float4 h1 = *(const float4*)&sm[S_H1 + (base+1)*64 + k4];
      float4 h2 = *(const float4*)&sm[S_H1 + (base+2)*64 + k4];
      float4 h3 = *(const float4*)&sm[S_H1 + (base+3)*64 + k4];
      #pragma unroll
      for (int u = 0; u < 4; u++) {
        float2 wv = *(const float2*)&sm[S_W2 + (k4+u)*64 + 2*lane];
        float f0 = (&h0.x)[u], f1 = (&h1.x)[u], f2 = (&h2.x)[u], f3 = (&h3.x)[u];
        ax[0] += f0*wv.x; ay[0] += f0*wv.y;
        ax[1] += f1*wv.x; ay[1] += f1*wv.y;
        ax[2] += f2*wv.x; ay[2] += f2*wv.y;
        ax[3] += f3*wv.x; ay[3] += f3*wv.y;
      }
    }
    #pragma unroll
    for (int r = 0; r < 4; r++)
      *(float2*)&sm[S_WH + (base+r)*64 + 2*lane] = make_float2(ax[r], ay[r]);
  }
  __syncthreads();

  // ---------------- stage 5: s2/t2 from Wh2, a2 ------------------------
  {
    float aI0 = gA2[lane],      aI1 = gA2[32 + lane];
    float aJ0 = gA2[64 + lane], aJ1 = gA2[96 + lane];
    for (int r = 0; r < 16; r++) {
      int i = w*16 + r;
      float x0 = sm[S_WH + i*64 + lane], x1 = sm[S_WH + i*64 + 32 + lane];
      float sp = wsum(x0*aI0 + x1*aI1);
      float tp = wsum(x0*aJ0 + x1*aJ1);
      if (lane == 0) { sm[S_S + i] = sp; sm[S_T + i] = tp; }
    }
  }
  __syncthreads();

  // ---------------- stage 6: GAT layer 2 + residual + LN + head -------
  for (int g = 0; g < 4; g++) {
    const int base = g*32 + w*4;
    float scale[4];
    #pragma unroll
    for (int r = 0; r < 4; r++) {
      const int i = base + r;
      const float si = sm[S_S + i];
      float e[4], av[4];
      float m = -1e30f;
      #pragma unroll
      for (int jj = 0; jj < 4; jj++) {
        int j = jj*32 + lane;
        float ee = si + sm[S_T + j];
        ee = fmaxf(ee, 0.2f*ee);
        float a = __ldg(&gAdj[i*128 + j]);
        e[jj] = ee; av[jj] = a;
        m = fmaxf(m, a > 0.f ? ee : -1e30f);
      }
      m = wmax(m);
      float Sl = 0.f, Tl = 0.f;
      #pragma unroll
      for (int jj = 0; jj < 4; jj++) {
        float p = av[jj] > 0.f ? __expf(e[jj] - m) : 0.f;
        float q = av[jj] * p;
        Sl += p; Tl += q;
        sm[S_Q + (w*4 + r)*128 + jj*32 + lane] = q;
      }
      Sl = wsum(Sl); Tl = wsum(Tl);
      scale[r] = 1.f / (Tl + 1e-8f * Sl);
    }
    __syncwarp();
    float ax[4] = {0,0,0,0}, ay[4] = {0,0,0,0};
    const float* qbase = &sm[S_Q + w*4*128];
    for (int j4 = 0; j4 < 128; j4 += 4) {
      float4 q0 = *(const float4*)(qbase + 0*128 + j4);
      float4 q1 = *(const float4*)(qbase + 1*128 + j4);
      float4 q2 = *(const float4*)(qbase + 2*128 + j4);
      float4 q3 = *(const float4*)(qbase + 3*128 + j4);
      #pragma unroll
      for (int u = 0; u < 4; u++) {
        float2 whv = *(const float2*)&sm[S_WH + (j4+u)*64 + 2*lane];
        float f0 = (&q0.x)[u], f1 = (&q1.x)[u], f2 = (&q2.x)[u], f3 = (&q3.x)[u];
        ax[0] += f0*whv.x; ay[0] += f0*whv.y;
        ax[1] += f1*whv.x; ay[1] += f1*whv.y;
        ax[2] += f2*whv.x; ay[2] += f2*whv.y;
        ax[3] += f3*whv.x; ay[3] += f3*whv.y;
      }
    }
    #pragma unroll
    for (int r = 0; r < 4; r++) {
      const int i = base + r;
      float2 h1v = *(const float2*)&sm[S_H1 + i*64 + 2*lane];
      float v0 = fmaxf(ax[r]*scale[r] + h1v.x, 0.f);   // relu(h2 + h1)
      float v1 = fmaxf(ay[r]*scale[r] + h1v.y, 0.f);
      float mu  = wsum(v0 + v1) * (1.f/64.f);
      float d0 = v0 - mu, d1 = v1 - mu;
      float var = wsum(d0*d0 + d1*d1) * (1.f/64.f);
      float inv = rsqrtf(var + 1e-5f);
      float y0 = d0*inv*__ldg(&gLn2g[2*lane])   + __ldg(&gLn2b[2*lane]);
      float y1 = d1*inv*__ldg(&gLn2g[2*lane+1]) + __ldg(&gLn2b[2*lane+1]);
      float pd = y0*__ldg(&gHgw[2*lane]) + y1*__ldg(&gHgw[2*lane+1]);
      pd = wsum(pd);
      if (lane == 0) atomicAdd(&sm[S_ACC], pd);
    }
    __syncwarp();
  }
  __syncthreads();

  // ---------------- final combine -------------------------------------
  if (tid == 0) {
    float qgat = sm[S_ACC] * (1.f/128.f) + gHgb[0];   // mean over nodes @ head
    float qmlp = gHmb[0], gp = gG2b[0];
    #pragma unroll 8
    for (int h = 0; h < 64; h++) {
      qmlp += sm[S_Y  + h] * __ldg(&gHmw[h]);
      gp   += sm[S_G1 + h] * __ldg(&gG2w[h]);
    }
    float gate = 1.f / (1.f + __expf(-gp));
    gOut[b] = qmlp + gate * qgat;                      // GAT_SCALE = 1
  }
}

extern "C" void kernel_launch(void* const* d_in, const int* in_sizes, int n_in,
                              void* d_out, int out_size) {
  (void)n_in; (void)out_size;
  const int B = in_sizes[0] / 128;
  const size_t smem = SMEM_FLOATS * sizeof(float);
  cudaFuncSetAttribute(graphmixer_kernel,
                       cudaFuncAttributeMaxDynamicSharedMemorySize, (int)smem);
  graphmixer_kernel<<<B, 256, smem>>>(
      (const float*)d_in[0],  (const float*)d_in[1],  (const float*)d_in[2],
      (const float*)d_in[3],  (const float*)d_in[4],  (const float*)d_in[5],
      (const float*)d_in[6],  (const float*)d_in[7],  (const float*)d_in[8],
      (const float*)d_in[9],  (const float*)d_in[10], (const float*)d_in[11],
      (const float*)d_in[12], (const float*)d_in[13], (const float*)d_in[14],
      (const float*)d_in[15], (const float*)d_in[16], (const float*)d_in[17],
      (const float*)d_in[18], (const float*)d_in[19], (const float*)d_in[20],
      (const float*)d_in[21], (const float*)d_in[22], (float*)d_out);
}

// round 4
// speedup vs baseline: 1.3113x; 1.3113x over previous
#include <cuda_runtime.h>

#define FULL 0xffffffffu

__device__ __forceinline__ float wsum(float v){
  #pragma unroll
  for (int o = 16; o; o >>= 1) v += __shfl_xor_sync(FULL, v, o);
  return v;
}
__device__ __forceinline__ float wmax(float v){
  #pragma unroll
  for (int o = 16; o; o >>= 1) v = fmaxf(v, __shfl_xor_sync(FULL, v, o));
  return v;
}

// ---- shared memory layout (floats) ----
#define S_WH    0                    // 128x64 : Wh1, later Wh2
#define S_H1    (S_WH  + 128*64)     // 128x64 : h1 (post-LN)
#define S_Q     (S_H1  + 128*64)     // 8 warps x 8 rows x 128
#define S_C     (S_Q   + 8*8*128)    // 128
#define S_S     (S_C   + 128)        // 128
#define S_T     (S_S   + 128)        // 128
#define S_W1    (S_T   + 128)        // 9x64 = 576
#define S_EMB   (S_W1  + 576)        // 128x8 = 1024
#define S_XM    (S_EMB + 1024)       // 64
#define S_G1    (S_XM  + 64)         // 64
#define S_Y     (S_G1  + 64)         // 64
#define S_PD    (S_Y   + 64)         // 8 per-warp head partials
#define SMEM_FLOATS (S_PD + 8)

__global__ void __launch_bounds__(256, 2)
graphmixer_kernel(const float* __restrict__ gC,   const float* __restrict__ gAdj,
                  const float* __restrict__ gEmb, const float* __restrict__ gW1,
                  const float* __restrict__ gA1,  const float* __restrict__ gW2,
                  const float* __restrict__ gA2,  const float* __restrict__ gLn1g,
                  const float* __restrict__ gLn1b,const float* __restrict__ gLn2g,
                  const float* __restrict__ gLn2b,const float* __restrict__ gHgw,
                  const float* __restrict__ gHgb, const float* __restrict__ gM1w,
                  const float* __restrict__ gM1b, const float* __restrict__ gM2w,
                  const float* __restrict__ gM2b, const float* __restrict__ gHmw,
                  const float* __restrict__ gHmb, const float* __restrict__ gG1w,
                  const float* __restrict__ gG1b, const float* __restrict__ gG2w,
                  const float* __restrict__ gG2b, float* __restrict__ gOut)
{
  extern __shared__ float sm[];
  const int tid  = threadIdx.x;
  const int w    = tid >> 5;
  const int lane = tid & 31;
  const int b    = blockIdx.x;

  // hoisted per-lane constants (2 feature columns per lane)
  const float lg0 = __ldg(&gLn1g[2*lane]),   lg1 = __ldg(&gLn1g[2*lane+1]);
  const float lb0 = __ldg(&gLn1b[2*lane]),   lb1 = __ldg(&gLn1b[2*lane+1]);
  const float mg0 = __ldg(&gLn2g[2*lane]),   mg1 = __ldg(&gLn2g[2*lane+1]);
  const float mb0 = __ldg(&gLn2b[2*lane]),   mb1 = __ldg(&gLn2b[2*lane+1]);
  const float hg0 = __ldg(&gHgw[2*lane]),    hg1 = __ldg(&gHgw[2*lane+1]);

  // ---------------- stage 0: stage constants into SMEM ----------------
  if (tid < 128) sm[S_C + tid] = gC[b*128 + tid];
  for (int i = tid; i < 576;  i += 256) sm[S_W1  + i] = gW1[i];
  for (int i = tid; i < 1024; i += 256) sm[S_EMB + i] = gEmb[i];
  __syncthreads();

  // ---------------- stage 1: Wh1 = [c | emb] @ W1  (128x9 @ 9x64) -----
  for (int idx = tid; idx < 8192; idx += 256) {
    int n = idx >> 6, h = idx & 63;
    float v = sm[S_C + n] * sm[S_W1 + h];
    #pragma unroll
    for (int d = 0; d < 8; d++)
      v += sm[S_EMB + n*8 + d] * sm[S_W1 + (d+1)*64 + h];
    sm[S_WH + idx] = v;
  }
  // MLP / gate hidden layers (only depend on sC)
  if (tid < 64) {
    float acc = gM1b[tid];
    #pragma unroll 4
    for (int n = 0; n < 128; n++) acc += sm[S_C + n] * __ldg(&gM1w[n*64 + tid]);
    sm[S_XM + tid] = fmaxf(acc, 0.f);
  } else if (tid < 128) {
    int h = tid - 64;
    float acc = gG1b[h];
    #pragma unroll 4
    for (int n = 0; n < 128; n++) acc += sm[S_C + n] * __ldg(&gG1w[n*64 + h]);
    sm[S_G1 + h] = fmaxf(acc, 0.f);
  }
  __syncthreads();

  // ---------------- stage 2: s1/t1 = Wh1 @ a_i, Wh1 @ a_j -------------
  {
    float aI0 = gA1[lane],      aI1 = gA1[32 + lane];
    float aJ0 = gA1[64 + lane], aJ1 = gA1[96 + lane];
    for (int r = 0; r < 16; r++) {
      int i = w*16 + r;
      float x0 = sm[S_WH + i*64 + lane], x1 = sm[S_WH + i*64 + 32 + lane];
      float sp = wsum(x0*aI0 + x1*aI1);
      float tp = wsum(x0*aJ0 + x1*aJ1);
      if (lane == 0) { sm[S_S + i] = sp; sm[S_T + i] = tp; }
    }
  }
  // MLP second layer
  if (tid < 64) {
    float acc = gM2b[tid];
    #pragma unroll 8
    for (int k = 0; k < 64; k++) acc += sm[S_XM + k] * __ldg(&gM2w[k*64 + tid]);
    sm[S_Y + tid] = fmaxf(acc, 0.f);
  }
  __syncthreads();

  // ---------------- stage 3: GAT layer 1 (attn + agg + elu + LN) ------
  #pragma unroll 1
  for (int g = 0; g < 2; g++) {
    const int base = w*16 + g*8;            // 8 rows per warp per pass
    const float tv0 = sm[S_T + lane],      tv1 = sm[S_T + 32 + lane];
    const float tv2 = sm[S_T + 64 + lane], tv3 = sm[S_T + 96 + lane];
    float scale[8];
    #pragma unroll
    for (int r = 0; r < 8; r++) {
      const int i = base + r;
      const float si = sm[S_S + i];
      float e[4], av[4];
      float m = -1e30f;
      const float tv[4] = {tv0, tv1, tv2, tv3};
      #pragma unroll
      for (int jj = 0; jj < 4; jj++) {
        float ee = si + tv[jj];
        ee = fmaxf(ee, 0.2f*ee);            // leaky_relu(x, 0.2)
        float a = __ldg(&gAdj[i*128 + jj*32 + lane]);
        e[jj] = ee; av[jj] = a;
        if (a > 0.f) m = fmaxf(m, ee);
      }
      m = wmax(m);
      float Sl = 0.f, Tl = 0.f;
      #pragma unroll
      for (int jj = 0; jj < 4; jj++) {
        float p = av[jj] > 0.f ? __expf(e[jj] - m) : 0.f;
        float qv = av[jj] * p;
        Sl += p; Tl += qv;
        sm[S_Q + (w*8 + r)*128 + jj*32 + lane] = qv;
      }
      Sl = wsum(Sl); Tl = wsum(Tl);
      scale[r] = __fdividef(1.f, Tl + 1e-8f * Sl);
    }
    __syncwarp();
    float ax[8] = {0,0,0,0,0,0,0,0}, ay[8] = {0,0,0,0,0,0,0,0};
    const float* qb = &sm[S_Q + (w << 10)];
    #pragma unroll 2
    for (int j4 = 0; j4 < 128; j4 += 4) {
      float4 q[8];
      #pragma unroll
      for (int r = 0; r < 8; r++) q[r] = *(const float4*)(qb + r*128 + j4);
      #pragma unroll
      for (int u = 0; u < 4; u++) {
        float2 whv = *(const float2*)&sm[S_WH + (j4+u)*64 + 2*lane];
        #pragma unroll
        for (int r = 0; r < 8; r++) {
          float f = (&q[r].x)[u];
          ax[r] += f*whv.x; ay[r] += f*whv.y;
        }
      }
    }
    #pragma unroll
    for (int r = 0; r < 8; r++) {
      float v0 = ax[r]*scale[r], v1 = ay[r]*scale[r];
      v0 = v0 > 0.f ? v0 : expm1f(v0);       // elu
      v1 = v1 > 0.f ? v1 : expm1f(v1);
      float mu  = wsum(v0 + v1) * (1.f/64.f);
      float d0 = v0 - mu, d1 = v1 - mu;
      float var = wsum(d0*d0 + d1*d1) * (1.f/64.f);
      float inv = rsqrtf(var + 1e-5f);
      *(float2*)&sm[S_H1 + (base+r)*64 + 2*lane] =
          make_float2(d0*inv*lg0 + lb0, d1*inv*lg1 + lb1);
    }
    __syncwarp();
  }
  __syncthreads();

  // ------- stage 4: Wh2 = h1 @ W2 (W2 via LDG) + fused s2/t2 ----------
  {
    const float aIx = __ldg(&gA2[2*lane]),    aIy = __ldg(&gA2[2*lane+1]);
    const float aJx = __ldg(&gA2[64+2*lane]), aJy = __ldg(&gA2[65+2*lane]);
    #pragma unroll 1
    for (int g = 0; g < 2; g++) {
      const int base = w*16 + g*8;
      float ax[8] = {0,0,0,0,0,0,0,0}, ay[8] = {0,0,0,0,0,0,0,0};
      #pragma unroll 2
      for (int k4 = 0; k4 < 64; k4 += 4) {
        float4 hr[8];
        #pragma unroll
        for (int r = 0; r < 8; r++)
          hr[r] = *(const float4*)&sm[S_H1 + (base+r)*64 + k4];
        #pragma unroll
        for (int u = 0; u < 4; u++) {
          float2 wv = __ldg((const float2*)&gW2[(k4+u)*64 + 2*lane]);
          #pragma unroll
          for (int r = 0; r < 8; r++) {
            float f = (&hr[r].x)[u];
            ax[r] += f*wv.x; ay[r] += f*wv.y;
          }
        }
      }
      #pragma unroll
      for (int r = 0; r < 8; r++) {
        *(float2*)&sm[S_WH + (base+r)*64 + 2*lane] = make_float2(ax[r], ay[r]);
        float sp = wsum(ax[r]*aIx + ay[r]*aIy);
        float tp = wsum(ax[r]*aJx + ay[r]*aJy);
        if (lane == 0) { sm[S_S + base + r] = sp; sm[S_T + base + r] = tp; }
      }
    }
  }
  __syncthreads();

  // ---------------- stage 6: GAT layer 2 + residual + LN + head -------
  float wpd = 0.f;
  #pragma unroll 1
  for (int g = 0; g < 2; g++) {
    const int base = w*16 + g*8;
    const float tv0 = sm[S_T + lane],      tv1 = sm[S_T + 32 + lane];
    const float tv2 = sm[S_T + 64 + lane], tv3 = sm[S_T + 96 + lane];
    float scale[8];
    #pragma unroll
    for (int r = 0; r < 8; r++) {
      const int i = base + r;
      const float si = sm[S_S + i];
      float e[4], av[4];
      float m = -1e30f;
      const float tv[4] = {tv0, tv1, tv2, tv3};
      #pragma unroll
      for (int jj = 0; jj < 4; jj++) {
        float ee = si + tv[jj];
        ee = fmaxf(ee, 0.2f*ee);
        float a = __ldg(&gAdj[i*128 + jj*32 + lane]);
        e[jj] = ee; av[jj] = a;
        if (a > 0.f) m = fmaxf(m, ee);
      }
      m = wmax(m);
      float Sl = 0.f, Tl = 0.f;
      #pragma unroll
      for (int jj = 0; jj < 4; jj++) {
        float p = av[jj] > 0.f ? __expf(e[jj] - m) : 0.f;
        float qv = av[jj] * p;
        Sl += p; Tl += qv;
        sm[S_Q + (w*8 + r)*128 + jj*32 + lane] = qv;
      }
      Sl = wsum(Sl); Tl = wsum(Tl);
      scale[r] = __fdividef(1.f, Tl + 1e-8f * Sl);
    }
    __syncwarp();
    float ax[8] = {0,0,0,0,0,0,0,0}, ay[8] = {0,0,0,0,0,0,0,0};
    const float* qb = &sm[S_Q + (w << 10)];
    #pragma unroll 2
    for (int j4 = 0; j4 < 128; j4 += 4) {
      float4 q[8];
      #pragma unroll
      for (int r = 0; r < 8; r++) q[r] = *(const float4*)(qb + r*128 + j4);
      #pragma unroll
      for (int u = 0; u < 4; u++) {
        float2 whv = *(const float2*)&sm[S_WH + (j4+u)*64 + 2*lane];
        #pragma unroll
        for (int r = 0; r < 8; r++) {
          float f = (&q[r].x)[u];
          ax[r] += f*whv.x; ay[r] += f*whv.y;
        }
      }
    }
    #pragma unroll
    for (int r = 0; r < 8; r++) {
      float2 h1v = *(const float2*)&sm[S_H1 + (base+r)*64 + 2*lane];
      float v0 = fmaxf(ax[r]*scale[r] + h1v.x, 0.f);   // relu(h2 + h1)
      float v1 = fmaxf(ay[r]*scale[r] + h1v.y, 0.f);
      float mu  = wsum(v0 + v1) * (1.f/64.f);
      float d0 = v0 - mu, d1 = v1 - mu;
      float var = wsum(d0*d0 + d1*d1) * (1.f/64.f);
      float inv = rsqrtf(var + 1e-5f);
      float y0 = d0*inv*mg0 + mb0;
      float y1 = d1*inv*mg1 + mb1;
      wpd += wsum(y0*hg0 + y1*hg1);                    // head dot, per row
    }
    __syncwarp();
  }
  if (lane == 0) sm[S_PD + w] = wpd;
  __syncthreads();

  // ---------------- final combine (warp 0, deterministic) -------------
  if (w == 0) {
    float qm = sm[S_Y  + lane]*__ldg(&gHmw[lane])
             + sm[S_Y  + 32 + lane]*__ldg(&gHmw[32 + lane]);
    float gp = sm[S_G1 + lane]*__ldg(&gG2w[lane])
             + sm[S_G1 + 32 + lane]*__ldg(&gG2w[32 + lane]);
    float ac = (lane < 8) ? sm[S_PD + lane] : 0.f;
    qm = wsum(qm); gp = wsum(gp); ac = wsum(ac);
    if (lane == 0) {
      float qgat = ac * (1.f/128.f) + gHgb[0];
      float qmlp = qm + gHmb[0];
      float gv   = gp + gG2b[0];
      float gate = __fdividef(1.f, 1.f + __expf(-gv));
      gOut[b] = qmlp + gate * qgat;                    // GAT_SCALE = 1
    }
  }
}

extern "C" void kernel_launch(void* const* d_in, const int* in_sizes, int n_in,
                              void* d_out, int out_size) {
  (void)n_in; (void)out_size;
  const int B = in_sizes[0] / 128;
  const size_t smem = SMEM_FLOATS * sizeof(float);
  cudaFuncSetAttribute(graphmixer_kernel,
                       cudaFuncAttributeMaxDynamicSharedMemorySize, (int)smem);
  graphmixer_kernel<<<B, 256, smem>>>(
      (const float*)d_in[0],  (const float*)d_in[1],  (const float*)d_in[2],
      (const float*)d_in[3],  (const float*)d_in[4],  (const float*)d_in[5],
      (const float*)d_in[6],  (const float*)d_in[7],  (const float*)d_in[8],
      (const float*)d_in[9],  (const float*)d_in[10], (const float*)d_in[11],
      (const float*)d_in[12], (const float*)d_in[13], (const float*)d_in[14],
      (const float*)d_in[15], (const float*)d_in[16], (const float*)d_in[17],
      (const float*)d_in[18], (const float*)d_in[19], (const float*)d_in[20],
      (const float*)d_in[21], (const float*)d_in[22], (float*)d_out);
}

// round 5
// speedup vs baseline: 1.3126x; 1.0010x over previous
#include <cuda_runtime.h>

#define FULL 0xffffffffu

__device__ __forceinline__ float wsum(float v){
  #pragma unroll
  for (int o = 16; o; o >>= 1) v += __shfl_xor_sync(FULL, v, o);
  return v;
}
__device__ __forceinline__ float wmax(float v){
  #pragma unroll
  for (int o = 16; o; o >>= 1) v = fmaxf(v, __shfl_xor_sync(FULL, v, o));
  return v;
}

// ---- shared memory layout (floats) ----
#define S_WH    0                    // 128x64 : Wh1, later Wh2
#define S_H1    (S_WH  + 128*64)     // 128x64 : h1 (post-LN)
#define S_Q     (S_H1  + 128*64)     // 8 warps x 8 rows x 128
#define S_C     (S_Q   + 8*8*128)    // 128
#define S_S     (S_C   + 128)        // 128
#define S_T     (S_S   + 128)        // 128
#define S_W1    (S_T   + 128)        // 9x64 = 576
#define S_EMB   (S_W1  + 576)        // 128x8 = 1024
#define S_XM    (S_EMB + 1024)       // 64
#define S_G1    (S_XM  + 64)         // 64
#define S_Y     (S_G1  + 64)         // 64
#define S_PD    (S_Y   + 64)         // 8 per-warp head partials
#define SMEM_FLOATS (S_PD + 8)

__global__ void __launch_bounds__(256, 2)
graphmixer_kernel(const float* __restrict__ gC,   const float* __restrict__ gAdj,
                  const float* __restrict__ gEmb, const float* __restrict__ gW1,
                  const float* __restrict__ gA1,  const float* __restrict__ gW2,
                  const float* __restrict__ gA2,  const float* __restrict__ gLn1g,
                  const float* __restrict__ gLn1b,const float* __restrict__ gLn2g,
                  const float* __restrict__ gLn2b,const float* __restrict__ gHgw,
                  const float* __restrict__ gHgb, const float* __restrict__ gM1w,
                  const float* __restrict__ gM1b, const float* __restrict__ gM2w,
                  const float* __restrict__ gM2b, const float* __restrict__ gHmw,
                  const float* __restrict__ gHmb, const float* __restrict__ gG1w,
                  const float* __restrict__ gG1b, const float* __restrict__ gG2w,
                  const float* __restrict__ gG2b, float* __restrict__ gOut)
{
  extern __shared__ float sm[];
  const int tid  = threadIdx.x;
  const int w    = tid >> 5;
  const int lane = tid & 31;
  const int b    = blockIdx.x;

  // hoisted per-lane constants (2 feature columns per lane)
  const float lg0 = __ldg(&gLn1g[2*lane]),   lg1 = __ldg(&gLn1g[2*lane+1]);
  const float lb0 = __ldg(&gLn1b[2*lane]),   lb1 = __ldg(&gLn1b[2*lane+1]);
  const float mg0 = __ldg(&gLn2g[2*lane]),   mg1 = __ldg(&gLn2g[2*lane+1]);
  const float mb0 = __ldg(&gLn2b[2*lane]),   mb1 = __ldg(&gLn2b[2*lane+1]);
  const float hg0 = __ldg(&gHgw[2*lane]),    hg1 = __ldg(&gHgw[2*lane+1]);

  // ---------------- stage 0: stage constants into SMEM ----------------
  if (tid < 128) sm[S_C + tid] = gC[b*128 + tid];
  for (int i = tid; i < 576;  i += 256) sm[S_W1  + i] = gW1[i];
  for (int i = tid; i < 1024; i += 256) sm[S_EMB + i] = gEmb[i];
  __syncthreads();

  // ---------------- stage 1: Wh1 = [c | emb] @ W1  (128x9 @ 9x64) -----
  for (int idx = tid; idx < 8192; idx += 256) {
    int n = idx >> 6, h = idx & 63;
    float v = sm[S_C + n] * sm[S_W1 + h];
    #pragma unroll
    for (int d = 0; d < 8; d++)
      v += sm[S_EMB + n*8 + d] * sm[S_W1 + (d+1)*64 + h];
    sm[S_WH + idx] = v;
  }
  // MLP / gate hidden layers (only depend on sC)
  if (tid < 64) {
    float acc = gM1b[tid];
    #pragma unroll 4
    for (int n = 0; n < 128; n++) acc += sm[S_C + n] * __ldg(&gM1w[n*64 + tid]);
    sm[S_XM + tid] = fmaxf(acc, 0.f);
  } else if (tid < 128) {
    int h = tid - 64;
    float acc = gG1b[h];
    #pragma unroll 4
    for (int n = 0; n < 128; n++) acc += sm[S_C + n] * __ldg(&gG1w[n*64 + h]);
    sm[S_G1 + h] = fmaxf(acc, 0.f);
  }
  __syncthreads();

  // ---------------- stage 2: s1/t1 = Wh1 @ a_i, Wh1 @ a_j -------------
  {
    float aI0 = gA1[lane],      aI1 = gA1[32 + lane];
    float aJ0 = gA1[64 + lane], aJ1 = gA1[96 + lane];
    for (int r = 0; r < 16; r++) {
      int i = w*16 + r;
      float x0 = sm[S_WH + i*64 + lane], x1 = sm[S_WH + i*64 + 32 + lane];
      float sp = wsum(x0*aI0 + x1*aI1);
      float tp = wsum(x0*aJ0 + x1*aJ1);
      if (lane == 0) { sm[S_S + i] = sp; sm[S_T + i] = tp; }
    }
  }
  // MLP second layer
  if (tid < 64) {
    float acc = gM2b[tid];
    #pragma unroll 8
    for (int k = 0; k < 64; k++) acc += sm[S_XM + k] * __ldg(&gM2w[k*64 + tid]);
    sm[S_Y + tid] = fmaxf(acc, 0.f);
  }
  __syncthreads();

  // ---------------- stage 3: GAT layer 1 (attn + agg + elu + LN) ------
  #pragma unroll 1
  for (int g = 0; g < 2; g++) {
    const int base = w*16 + g*8;            // 8 rows per warp per pass
    const float tv0 = sm[S_T + lane],      tv1 = sm[S_T + 32 + lane];
    const float tv2 = sm[S_T + 64 + lane], tv3 = sm[S_T + 96 + lane];
    float scale[8];
    #pragma unroll
    for (int r = 0; r < 8; r++) {
      const int i = base + r;
      const float si = sm[S_S + i];
      float e[4], av[4];
      float m = -1e30f;
      const float tv[4] = {tv0, tv1, tv2, tv3};
      #pragma unroll
      for (int jj = 0; jj < 4; jj++) {
        float ee = si + tv[jj];
        ee = fmaxf(ee, 0.2f*ee);            // leaky_relu(x, 0.2)
        float a = __ldg(&gAdj[i*128 + jj*32 + lane]);
        e[jj] = ee; av[jj] = a;
        if (a > 0.f) m = fmaxf(m, ee);
      }
      m = wmax(m);
      float Sl = 0.f, Tl = 0.f;
      #pragma unroll
      for (int jj = 0; jj < 4; jj++) {
        float p = av[jj] > 0.f ? __expf(e[jj] - m) : 0.f;
        float qv = av[jj] * p;
        Sl += p; Tl += qv;
        sm[S_Q + (w*8 + r)*128 + jj*32 + lane] = qv;
      }
      Sl = wsum(Sl); Tl = wsum(Tl);
      scale[r] = __fdividef(1.f, Tl + 1e-8f * Sl);
    }
    __syncwarp();
    float ax[8] = {0,0,0,0,0,0,0,0}, ay[8] = {0,0,0,0,0,0,0,0};
    const float* qb = &sm[S_Q + (w << 10)];
    #pragma unroll 2
    for (int j4 = 0; j4 < 128; j4 += 4) {
      float4 q[8];
      #pragma unroll
      for (int r = 0; r < 8; r++) q[r] = *(const float4*)(qb + r*128 + j4);
      #pragma unroll
      for (int u = 0; u < 4; u++) {
        float2 whv = *(const float2*)&sm[S_WH + (j4+u)*64 + 2*lane];
        #pragma unroll
        for (int r = 0; r < 8; r++) {
          float f = (&q[r].x)[u];
          ax[r] += f*whv.x; ay[r] += f*whv.y;
        }
      }
    }
    #pragma unroll
    for (int r = 0; r < 8; r++) {
      float v0 = ax[r]*scale[r], v1 = ay[r]*scale[r];
      v0 = v0 > 0.f ? v0 : expm1f(v0);       // elu
      v1 = v1 > 0.f ? v1 : expm1f(v1);
      float mu  = wsum(v0 + v1) * (1.f/64.f);
      float d0 = v0 - mu, d1 = v1 - mu;
      float var = wsum(d0*d0 + d1*d1) * (1.f/64.f);
      float inv = rsqrtf(var + 1e-5f);
      *(float2*)&sm[S_H1 + (base+r)*64 + 2*lane] =
          make_float2(d0*inv*lg0 + lb0, d1*inv*lg1 + lb1);
    }
    __syncwarp();
  }
  __syncthreads();

  // ------- stage 4: Wh2 = h1 @ W2 (W2 via LDG) + fused s2/t2 ----------
  {
    const float aIx = __ldg(&gA2[2*lane]),    aIy = __ldg(&gA2[2*lane+1]);
    const float aJx = __ldg(&gA2[64+2*lane]), aJy = __ldg(&gA2[65+2*lane]);
    #pragma unroll 1
    for (int g = 0; g < 2; g++) {
      const int base = w*16 + g*8;
      float ax[8] = {0,0,0,0,0,0,0,0}, ay[8] = {0,0,0,0,0,0,0,0};
      #pragma unroll 2
      for (int k4 = 0; k4 < 64; k4 += 4) {
        float4 hr[8];
        #pragma unroll
        for (int r = 0; r < 8; r++)
          hr[r] = *(const float4*)&sm[S_H1 + (base+r)*64 + k4];
        #pragma unroll
        for (int u = 0; u < 4; u++) {
          float2 wv = __ldg((const float2*)&gW2[(k4+u)*64 + 2*lane]);
          #pragma unroll
          for (int r = 0; r < 8; r++) {
            float f = (&hr[r].x)[u];
            ax[r] += f*wv.x; ay[r] += f*wv.y;
          }
        }
      }
      #pragma unroll
      for (int r = 0; r < 8; r++) {
        *(float2*)&sm[S_WH + (base+r)*64 + 2*lane] = make_float2(ax[r], ay[r]);
        float sp = wsum(ax[r]*aIx + ay[r]*aIy);
        float tp = wsum(ax[r]*aJx + ay[r]*aJy);
        if (lane == 0) { sm[S_S + base + r] = sp; sm[S_T + base + r] = tp; }
      }
    }
  }
  __syncthreads();

  // ---------------- stage 6: GAT layer 2 + residual + LN + head -------
  float wpd = 0.f;
  #pragma unroll 1
  for (int g = 0; g < 2; g++) {
    const int base = w*16 + g*8;
    const float tv0 = sm[S_T + lane],      tv1 = sm[S_T + 32 + lane];
    const float tv2 = sm[S_T + 64 + lane], tv3 = sm[S_T + 96 + lane];
    float scale[8];
    #pragma unroll
    for (int r = 0; r < 8; r++) {
      const int i = base + r;
      const float si = sm[S_S + i];
      float e[4], av[4];
      float m = -1e30f;
      const float tv[4] = {tv0, tv1, tv2, tv3};
      #pragma unroll
      for (int jj = 0; jj < 4; jj++) {
        float ee = si + tv[jj];
        ee = fmaxf(ee, 0.2f*ee);
        float a = __ldg(&gAdj[i*128 + jj*32 + lane]);
        e[jj] = ee; av[jj] = a;
        if (a > 0.f) m = fmaxf(m, ee);
      }
      m = wmax(m);
      float Sl = 0.f, Tl = 0.f;
      #pragma unroll
      for (int jj = 0; jj < 4; jj++) {
        float p = av[jj] > 0.f ? __expf(e[jj] - m) : 0.f;
        float qv = av[jj] * p;
        Sl += p; Tl += qv;
        sm[S_Q + (w*8 + r)*128 + jj*32 + lane] = qv;
      }
      Sl = wsum(Sl); Tl = wsum(Tl);
      scale[r] = __fdividef(1.f, Tl + 1e-8f * Sl);
    }
    __syncwarp();
    float ax[8] = {0,0,0,0,0,0,0,0}, ay[8] = {0,0,0,0,0,0,0,0};
    const float* qb = &sm[S_Q + (w << 10)];
    #pragma unroll 2
    for (int j4 = 0; j4 < 128; j4 += 4) {
      float4 q[8];
      #pragma unroll
      for (int r = 0; r < 8; r++) q[r] = *(const float4*)(qb + r*128 + j4);
      #pragma unroll
      for (int u = 0; u < 4; u++) {
        float2 whv = *(const float2*)&sm[S_WH + (j4+u)*64 + 2*lane];
        #pragma unroll
        for (int r = 0; r < 8; r++) {
          float f = (&q[r].x)[u];
          ax[r] += f*whv.x; ay[r] += f*whv.y;
        }
      }
    }
    #pragma unroll
    for (int r = 0; r < 8; r++) {
      float2 h1v = *(const float2*)&sm[S_H1 + (base+r)*64 + 2*lane];
      float v0 = fmaxf(ax[r]*scale[r] + h1v.x, 0.f);   // relu(h2 + h1)
      float v1 = fmaxf(ay[r]*scale[r] + h1v.y, 0.f);
      float mu  = wsum(v0 + v1) * (1.f/64.f);
      float d0 = v0 - mu, d1 = v1 - mu;
      float var = wsum(d0*d0 + d1*d1) * (1.f/64.f);
      float inv = rsqrtf(var + 1e-5f);
      float y0 = d0*inv*mg0 + mb0;
      float y1 = d1*inv*mg1 + mb1;
      wpd += wsum(y0*hg0 + y1*hg1);                    // head dot, per row
    }
    __syncwarp();
  }
  if (lane == 0) sm[S_PD + w] = wpd;
  __syncthreads();

  // ---------------- final combine (warp 0, deterministic) -------------
  if (w == 0) {
    float qm = sm[S_Y  + lane]*__ldg(&gHmw[lane])
             + sm[S_Y  + 32 + lane]*__ldg(&gHmw[32 + lane]);
    float gp = sm[S_G1 + lane]*__ldg(&gG2w[lane])
             + sm[S_G1 + 32 + lane]*__ldg(&gG2w[32 + lane]);
    float ac = (lane < 8) ? sm[S_PD + lane] : 0.f;
    qm = wsum(qm); gp = wsum(gp); ac = wsum(ac);
    if (lane == 0) {
      float qgat = ac * (1.f/128.f) + gHgb[0];
      float qmlp = qm + gHmb[0];
      float gv   = gp + gG2b[0];
      float gate = __fdividef(1.f, 1.f + __expf(-gv));
      gOut[b] = qmlp + gate * qgat;                    // GAT_SCALE = 1
    }
  }
}

extern "C" void kernel_launch(void* const* d_in, const int* in_sizes, int n_in,
                              void* d_out, int out_size) {
  (void)n_in; (void)out_size;
  const int B = in_sizes[0] / 128;
  const size_t smem = SMEM_FLOATS * sizeof(float);
  cudaFuncSetAttribute(graphmixer_kernel,
                       cudaFuncAttributeMaxDynamicSharedMemorySize, (int)smem);
  graphmixer_kernel<<<B, 256, smem>>>(
      (const float*)d_in[0],  (const float*)d_in[1],  (const float*)d_in[2],
      (const float*)d_in[3],  (const float*)d_in[4],  (const float*)d_in[5],
      (const float*)d_in[6],  (const float*)d_in[7],  (const float*)d_in[8],
      (const float*)d_in[9],  (const float*)d_in[10], (const float*)d_in[11],
      (const float*)d_in[12], (const float*)d_in[13], (const float*)d_in[14],
      (const float*)d_in[15], (const float*)d_in[16], (const float*)d_in[17],
      (const float*)d_in[18], (const float*)d_in[19], (const float*)d_in[20],
      (const float*)d_in[21], (const float*)d_in[22], (float*)d_out);
}

// round 6
// speedup vs baseline: 1.5371x; 1.1710x over previous
#include <cuda_runtime.h>

#define FULL 0xffffffffu

__device__ __forceinline__ float wsum(float v){
  #pragma unroll
  for (int o = 16; o; o >>= 1) v += __shfl_xor_sync(FULL, v, o);
  return v;
}

// ---- shared memory layout (floats) ----
#define S_WH    0                    // 128x64 : Wh1, later Wh2
#define S_H1    (S_WH  + 128*64)     // 128x64 : h1 (post-LN)
#define S_Q     (S_H1  + 128*64)     // 8 warps x 8 rows x 128 (lane-major)
#define S_C     (S_Q   + 8*8*128)    // 128
#define S_S     (S_C   + 128)        // 128
#define S_T     (S_S   + 128)        // 128
#define S_EMB   (S_T   + 128)        // 128x8 = 1024
#define S_XM    (S_EMB + 1024)       // 64
#define S_G1    (S_XM  + 64)         // 64
#define S_Y     (S_G1  + 64)         // 64
#define S_PD    (S_Y   + 64)         // 8 per-warp head partials
#define SMEM_FLOATS (S_PD + 8)

__global__ void __launch_bounds__(256, 2)
graphmixer_kernel(const float* __restrict__ gC,   const float* __restrict__ gAdj,
                  const float* __restrict__ gEmb, const float* __restrict__ gW1,
                  const float* __restrict__ gA1,  const float* __restrict__ gW2,
                  const float* __restrict__ gA2,  const float* __restrict__ gLn1g,
                  const float* __restrict__ gLn1b,const float* __restrict__ gLn2g,
                  const float* __restrict__ gLn2b,const float* __restrict__ gHgw,
                  const float* __restrict__ gHgb, const float* __restrict__ gM1w,
                  const float* __restrict__ gM1b, const float* __restrict__ gM2w,
                  const float* __restrict__ gM2b, const float* __restrict__ gHmw,
                  const float* __restrict__ gHmb, const float* __restrict__ gG1w,
                  const float* __restrict__ gG1b, const float* __restrict__ gG2w,
                  const float* __restrict__ gG2b, float* __restrict__ gOut)
{
  extern __shared__ float sm[];
  const int tid  = threadIdx.x;
  const int w    = tid >> 5;
  const int lane = tid & 31;
  const int b    = blockIdx.x;

  // hoisted per-lane constants (lane owns feature pair 2l, 2l+1)
  const float lg0 = __ldg(&gLn1g[2*lane]),   lg1 = __ldg(&gLn1g[2*lane+1]);
  const float lb0 = __ldg(&gLn1b[2*lane]),   lb1 = __ldg(&gLn1b[2*lane+1]);
  const float mg0 = __ldg(&gLn2g[2*lane]),   mg1 = __ldg(&gLn2g[2*lane+1]);
  const float mb0 = __ldg(&gLn2b[2*lane]),   mb1 = __ldg(&gLn2b[2*lane+1]);
  const float hg0 = __ldg(&gHgw[2*lane]),    hg1 = __ldg(&gHgw[2*lane+1]);

  // ---------------- stage 0: stage inputs into SMEM -------------------
  if (tid < 128) sm[S_C + tid] = gC[b*128 + tid];
  for (int i = tid; i < 1024; i += 256) sm[S_EMB + i] = gEmb[i];
  __syncthreads();

  // ------- stage 1: Wh1 = [c|emb] @ W1, fused s1/t1 epilogue ----------
  {
    float w1x[9], w1y[9];
    #pragma unroll
    for (int d = 0; d < 9; d++) {
      float2 t = __ldg((const float2*)&gW1[d*64 + 2*lane]);
      w1x[d] = t.x; w1y[d] = t.y;
    }
    const float aI0 = __ldg(&gA1[2*lane]),    aI1 = __ldg(&gA1[2*lane+1]);
    const float aJ0 = __ldg(&gA1[64+2*lane]), aJ1 = __ldg(&gA1[65+2*lane]);
    #pragma unroll 2
    for (int r = 0; r < 16; r++) {
      const int n = w*16 + r;
      const float c = sm[S_C + n];
      float4 e0 = *(const float4*)&sm[S_EMB + n*8];
      float4 e1 = *(const float4*)&sm[S_EMB + n*8 + 4];
      float x = c*w1x[0] + e0.x*w1x[1] + e0.y*w1x[2] + e0.z*w1x[3] + e0.w*w1x[4]
                         + e1.x*w1x[5] + e1.y*w1x[6] + e1.z*w1x[7] + e1.w*w1x[8];
      float y = c*w1y[0] + e0.x*w1y[1] + e0.y*w1y[2] + e0.z*w1y[3] + e0.w*w1y[4]
                         + e1.x*w1y[5] + e1.y*w1y[6] + e1.z*w1y[7] + e1.w*w1y[8];
      *(float2*)&sm[S_WH + n*64 + 2*lane] = make_float2(x, y);
      float sp = wsum(x*aI0 + y*aI1);
      float tp = wsum(x*aJ0 + y*aJ1);
      if (lane == 0) { sm[S_S + n] = sp; sm[S_T + n] = tp; }
    }
  }
  // MLP / gate hidden layers (depend only on c) — warps 0..3
  if (tid < 64) {
    float acc = gM1b[tid];
    #pragma unroll 4
    for (int n = 0; n < 128; n++) acc += sm[S_C + n] * __ldg(&gM1w[n*64 + tid]);
    sm[S_XM + tid] = fmaxf(acc, 0.f);
  } else if (tid < 128) {
    int h = tid - 64;
    float acc = gG1b[h];
    #pragma unroll 4
    for (int n = 0; n < 128; n++) acc += sm[S_C + n] * __ldg(&gG1w[n*64 + h]);
    sm[S_G1 + h] = fmaxf(acc, 0.f);
  }
  __syncthreads();

  // MLP second layer (overlaps with GAT layer 1 on other warps)
  if (tid < 64) {
    float acc = gM2b[tid];
    #pragma unroll 8
    for (int k = 0; k < 64; k++) acc += sm[S_XM + k] * __ldg(&gM2w[k*64 + tid]);
    sm[S_Y + tid] = fmaxf(acc, 0.f);
  }

  // ---------------- stage 3: GAT layer 1 (attn + agg + elu + LN) ------
  #pragma unroll 1
  for (int g = 0; g < 2; g++) {
    const int base = w*16 + g*8;            // 8 rows per warp per pass
    const float tv0 = sm[S_T + lane],      tv1 = sm[S_T + 32 + lane];
    const float tv2 = sm[S_T + 64 + lane], tv3 = sm[S_T + 96 + lane];
    float scale[8];
    #pragma unroll
    for (int r = 0; r < 8; r++) {
      const int i = base + r;
      const float si = sm[S_S + i];
      const float tv[4] = {tv0, tv1, tv2, tv3};
      float qv[4];
      float Sl = 0.f, Tl = 0.f;
      #pragma unroll
      for (int jj = 0; jj < 4; jj++) {
        float ee = si + tv[jj];
        ee = fmaxf(ee, 0.2f*ee);            // leaky_relu(x, 0.2)
        float a = __ldg(&gAdj[i*128 + jj*32 + lane]);
        float p = a > 0.f ? __expf(ee) : 0.f;   // no max-shift needed (|e| small)
        float q = a * p;
        Sl += p; Tl += q;
        qv[jj] = q;
      }
      *(float4*)&sm[S_Q + (w*8 + r)*128 + lane*4] =
          make_float4(qv[0], qv[1], qv[2], qv[3]);
      Sl = wsum(Sl); Tl = wsum(Tl);
      scale[r] = __fdividef(1.f, Tl + 1e-8f * Sl);
    }
    __syncwarp();
    float ax[8] = {0,0,0,0,0,0,0,0}, ay[8] = {0,0,0,0,0,0,0,0};
    const float* qb = &sm[S_Q + (w << 10)];
    #pragma unroll 2
    for (int j0 = 0; j0 < 32; j0++) {
      float4 q[8];
      #pragma unroll
      for (int r = 0; r < 8; r++) q[r] = *(const float4*)(qb + r*128 + j0*4);
      #pragma unroll
      for (int u = 0; u < 4; u++) {
        float2 whv = *(const float2*)&sm[S_WH + (u*32 + j0)*64 + 2*lane];
        #pragma unroll
        for (int r = 0; r < 8; r++) {
          float f = (&q[r].x)[u];
          ax[r] += f*whv.x; ay[r] += f*whv.y;
        }
      }
    }
    #pragma unroll
    for (int r = 0; r < 8; r++) {
      float v0 = ax[r]*scale[r], v1 = ay[r]*scale[r];
      v0 = v0 > 0.f ? v0 : __expf(v0) - 1.f;   // elu
      v1 = v1 > 0.f ? v1 : __expf(v1) - 1.f;
      float s1 = wsum(v0 + v1);
      float s2 = wsum(v0*v0 + v1*v1);          // independent chains
      float mu  = s1 * (1.f/64.f);
      float var = s2 * (1.f/64.f) - mu*mu;
      float inv = rsqrtf(var + 1e-5f);
      float d0 = v0 - mu, d1 = v1 - mu;
      *(float2*)&sm[S_H1 + (base+r)*64 + 2*lane] =
          make_float2(d0*inv*lg0 + lb0, d1*inv*lg1 + lb1);
    }
    __syncwarp();
  }
  __syncthreads();

  // ------- stage 4: Wh2 = h1 @ W2 (W2 via LDG) + fused s2/t2 ----------
  {
    const float aIx = __ldg(&gA2[2*lane]),    aIy = __ldg(&gA2[2*lane+1]);
    const float aJx = __ldg(&gA2[64+2*lane]), aJy = __ldg(&gA2[65+2*lane]);
    #pragma unroll 1
    for (int g = 0; g < 2; g++) {
      const int base = w*16 + g*8;
      float ax[8] = {0,0,0,0,0,0,0,0}, ay[8] = {0,0,0,0,0,0,0,0};
      #pragma unroll 2
      for (int k4 = 0; k4 < 64; k4 += 4) {
        float4 hr[8];
        #pragma unroll
        for (int r = 0; r < 8; r++)
          hr[r] = *(const float4*)&sm[S_H1 + (base+r)*64 + k4];
        #pragma unroll
        for (int u = 0; u < 4; u++) {
          float2 wv = __ldg((const float2*)&gW2[(k4+u)*64 + 2*lane]);
          #pragma unroll
          for (int r = 0; r < 8; r++) {
            float f = (&hr[r].x)[u];
            ax[r] += f*wv.x; ay[r] += f*wv.y;
          }
        }
      }
      #pragma unroll
      for (int r = 0; r < 8; r++) {
        *(float2*)&sm[S_WH + (base+r)*64 + 2*lane] = make_float2(ax[r], ay[r]);
        float sp = wsum(ax[r]*aIx + ay[r]*aIy);
        float tp = wsum(ax[r]*aJx + ay[r]*aJy);
        if (lane == 0) { sm[S_S + base + r] = sp; sm[S_T + base + r] = tp; }
      }
    }
  }
  __syncthreads();

  // ---------------- stage 6: GAT layer 2 + residual + LN + head -------
  float wpd = 0.f;
  #pragma unroll 1
  for (int g = 0; g < 2; g++) {
    const int base = w*16 + g*8;
    const float tv0 = sm[S_T + lane],      tv1 = sm[S_T + 32 + lane];
    const float tv2 = sm[S_T + 64 + lane], tv3 = sm[S_T + 96 + lane];
    float scale[8];
    #pragma unroll
    for (int r = 0; r < 8; r++) {
      const int i = base + r;
      const float si = sm[S_S + i];
      const float tv[4] = {tv0, tv1, tv2, tv3};
      float qv[4];
      float Sl = 0.f, Tl = 0.f;
      #pragma unroll
      for (int jj = 0; jj < 4; jj++) {
        float ee = si + tv[jj];
        ee = fmaxf(ee, 0.2f*ee);
        float a = __ldg(&gAdj[i*128 + jj*32 + lane]);
        float p = a > 0.f ? __expf(ee) : 0.f;
        float q = a * p;
        Sl += p; Tl += q;
        qv[jj] = q;
      }
      *(float4*)&sm[S_Q + (w*8 + r)*128 + lane*4] =
          make_float4(qv[0], qv[1], qv[2], qv[3]);
      Sl = wsum(Sl); Tl = wsum(Tl);
      scale[r] = __fdividef(1.f, Tl + 1e-8f * Sl);
    }
    __syncwarp();
    float ax[8] = {0,0,0,0,0,0,0,0}, ay[8] = {0,0,0,0,0,0,0,0};
    const float* qb = &sm[S_Q + (w << 10)];
    #pragma unroll 2
    for (int j0 = 0; j0 < 32; j0++) {
      float4 q[8];
      #pragma unroll
      for (int r = 0; r < 8; r++) q[r] = *(const float4*)(qb + r*128 + j0*4);
      #pragma unroll
      for (int u = 0; u < 4; u++) {
        float2 whv = *(const float2*)&sm[S_WH + (u*32 + j0)*64 + 2*lane];
        #pragma unroll
        for (int r = 0; r < 8; r++) {
          float f = (&q[r].x)[u];
          ax[r] += f*whv.x; ay[r] += f*whv.y;
        }
      }
    }
    #pragma unroll
    for (int r = 0; r < 8; r++) {
      float2 h1v = *(const float2*)&sm[S_H1 + (base+r)*64 + 2*lane];
      float v0 = fmaxf(ax[r]*scale[r] + h1v.x, 0.f);   // relu(h2 + h1)
      float v1 = fmaxf(ay[r]*scale[r] + h1v.y, 0.f);
      float s1 = wsum(v0 + v1);
      float s2 = wsum(v0*v0 + v1*v1);
      float mu  = s1 * (1.f/64.f);
      float var = s2 * (1.f/64.f) - mu*mu;
      float inv = rsqrtf(var + 1e-5f);
      float d0 = v0 - mu, d1 = v1 - mu;
      float y0 = d0*inv*mg0 + mb0;
      float y1 = d1*inv*mg1 + mb1;
      wpd += y0*hg0 + y1*hg1;              // defer cross-lane reduce
    }
    __syncwarp();
  }
  wpd = wsum(wpd);                          // one reduction for all 16 rows
  if (lane == 0) sm[S_PD + w] = wpd;
  __syncthreads();

  // ---------------- final combine (warp 0, deterministic) -------------
  if (w == 0) {
    float qm = sm[S_Y  + lane]*__ldg(&gHmw[lane])
             + sm[S_Y  + 32 + lane]*__ldg(&gHmw[32 + lane]);
    float gp = sm[S_G1 + lane]*__ldg(&gG2w[lane])
             + sm[S_G1 + 32 + lane]*__ldg(&gG2w[32 + lane]);
    float ac = (lane < 8) ? sm[S_PD + lane] : 0.f;
    qm = wsum(qm); gp = wsum(gp); ac = wsum(ac);
    if (lane == 0) {
      float qgat = ac * (1.f/128.f) + gHgb[0];
      float qmlp = qm + gHmb[0];
      float gv   = gp + gG2b[0];
      float gate = __fdividef(1.f, 1.f + __expf(-gv));
      gOut[b] = qmlp + gate * qgat;                    // GAT_SCALE = 1
    }
  }
}

extern "C" void kernel_launch(void* const* d_in, const int* in_sizes, int n_in,
                              void* d_out, int out_size) {
  (void)n_in; (void)out_size;
  const int B = in_sizes[0] / 128;
  const size_t smem = SMEM_FLOATS * sizeof(float);
  cudaFuncSetAttribute(graphmixer_kernel,
                       cudaFuncAttributeMaxDynamicSharedMemorySize, (int)smem);
  graphmixer_kernel<<<B, 256, smem>>>(
      (const float*)d_in[0],  (const float*)d_in[1],  (const float*)d_in[2],
      (const float*)d_in[3],  (const float*)d_in[4],  (const float*)d_in[5],
      (const float*)d_in[6],  (const float*)d_in[7],  (const float*)d_in[8],
      (const float*)d_in[9],  (const float*)d_in[10], (const float*)d_in[11],
      (const float*)d_in[12], (const float*)d_in[13], (const float*)d_in[14],
      (const float*)d_in[15], (const float*)d_in[16], (const float*)d_in[17],
      (const float*)d_in[18], (const float*)d_in[19], (const float*)d_in[20],
      (const float*)d_in[21], (const float*)d_in[22], (float*)d_out);
}